// round 1
// baseline (speedup 1.0000x reference)
#include <cuda_runtime.h>
#include <cstdint>

// ---------------- static device scratch (no allocations allowed) ----------------
__device__ float g_coreT[512 * 512];   // 1 MB : core transposed -> [lmn][ijk]
__device__ float g_T3[4096 * 512];     // 8 MB : in-contracted activations
__device__ float g_U [4096 * 512];     // 8 MB : core-contracted activations

// ---------------- K0: transpose core [512x512] -> g_coreT ----------------
__global__ __launch_bounds__(256) void k_transpose(const float* __restrict__ core) {
    __shared__ float tile[32][33];
    int bx = blockIdx.x * 32, by = blockIdx.y * 32;
    int tx = threadIdx.x, ty = threadIdx.y;
#pragma unroll
    for (int r = 0; r < 32; r += 8)
        tile[ty + r][tx] = core[(by + ty + r) * 512 + bx + tx];
    __syncthreads();
#pragma unroll
    for (int r = 0; r < 32; r += 8)
        g_coreT[(bx + ty + r) * 512 + by + tx] = tile[tx][ty + r];
}

// ---------------- K1: stage A (in-side contractions) ----------------
// Per block: 4 samples, 256 threads.
//   t1[l, e*16+f] = sum_d x[d*256+e*16+f] * f3[d*8+l]
//   t2[l, m*16+f] = sum_e t1[l, e*16+f]   * f4[e*8+m]
//   t3[l*64+m*8+n]= sum_f t2[l, m*16+f]   * f5[f*8+n]
// smem: t1s 4*2048, t2s 4*(8*136) (padded stride 136), factors 3*128
__global__ __launch_bounds__(256) void k_stageA(const float* __restrict__ x,
                                                const float* __restrict__ f3,
                                                const float* __restrict__ f4,
                                                const float* __restrict__ f5) {
    extern __shared__ float sm[];
    float* t1s = sm;                    // 4 * 2048
    float* t2s = sm + 4 * 2048;         // 4 * 1088  (8 * 136 per sample)
    float* f3s = t2s + 4 * 1088;
    float* f4s = f3s + 128;
    float* f5s = f4s + 128;

    int t = threadIdx.x;
    if (t < 128) { f3s[t] = f3[t]; f4s[t] = f4[t]; f5s[t] = f5[t]; }
    __syncthreads();

    long s0 = (long)blockIdx.x * 4;

    // ---- phase 1: t1 (one ef column per thread, 4 samples at once) ----
    {
        int ef = t;
        float acc[4][8];
#pragma unroll
        for (int s = 0; s < 4; s++)
#pragma unroll
            for (int l = 0; l < 8; l++) acc[s][l] = 0.f;
#pragma unroll
        for (int d = 0; d < 16; d++) {
            float xv0 = x[(s0 + 0) * 4096 + d * 256 + ef];
            float xv1 = x[(s0 + 1) * 4096 + d * 256 + ef];
            float xv2 = x[(s0 + 2) * 4096 + d * 256 + ef];
            float xv3 = x[(s0 + 3) * 4096 + d * 256 + ef];
#pragma unroll
            for (int l = 0; l < 8; l++) {
                float fv = f3s[d * 8 + l];
                acc[0][l] += xv0 * fv; acc[1][l] += xv1 * fv;
                acc[2][l] += xv2 * fv; acc[3][l] += xv3 * fv;
            }
        }
#pragma unroll
        for (int s = 0; s < 4; s++)
#pragma unroll
            for (int l = 0; l < 8; l++)
                t1s[s * 2048 + l * 256 + ef] = acc[s][l];
    }
    __syncthreads();

    // ---- phase 2: t2 ((l,f) pair per thread, 2 samples at once) ----
    {
        int h = t >> 7, pair = t & 127;
        int l = pair >> 4, f = pair & 15;
        float acc[2][8];
#pragma unroll
        for (int z = 0; z < 2; z++)
#pragma unroll
            for (int m = 0; m < 8; m++) acc[z][m] = 0.f;
#pragma unroll
        for (int e = 0; e < 16; e++) {
            float tv0 = t1s[(2 * h + 0) * 2048 + l * 256 + e * 16 + f];
            float tv1 = t1s[(2 * h + 1) * 2048 + l * 256 + e * 16 + f];
#pragma unroll
            for (int m = 0; m < 8; m++) {
                float fv = f4s[e * 8 + m];
                acc[0][m] += tv0 * fv; acc[1][m] += tv1 * fv;
            }
        }
#pragma unroll
        for (int z = 0; z < 2; z++)
#pragma unroll
            for (int m = 0; m < 8; m++)
                t2s[(2 * h + z) * 1088 + l * 136 + m * 16 + f] = acc[z][m];
    }
    __syncthreads();

    // ---- phase 3: t3 -> global ((l,m) pair per thread, sample = t>>6) ----
    {
        int q = t >> 6, pair = t & 63;
        int l = pair >> 3, m = pair & 7;
        float acc[8];
#pragma unroll
        for (int n = 0; n < 8; n++) acc[n] = 0.f;
#pragma unroll
        for (int f = 0; f < 16; f++) {
            float tv = t2s[q * 1088 + l * 136 + m * 16 + f];
#pragma unroll
            for (int n = 0; n < 8; n++) acc[n] += tv * f5s[f * 8 + n];
        }
        float* dst = g_T3 + (s0 + q) * 512 + l * 64 + m * 8;
        *(float4*)(dst + 0) = make_float4(acc[0], acc[1], acc[2], acc[3]);
        *(float4*)(dst + 4) = make_float4(acc[4], acc[5], acc[6], acc[7]);
    }
}

// ---------------- K2: stage B, U[N,512] = T3[N,512] * coreT[512,512] ----------------
// Per block: 32 samples x 512 cols, K=512 in chunks of 16. 256 threads.
// Thread owns 16 samples (half) x 4 consecutive cols. smem: As 64KB + Bs 32KB.
__global__ __launch_bounds__(256) void k_gemm() {
    extern __shared__ float sm[];
    float* As = sm;                  // 32 * 512
    float* Bs = sm + 32 * 512;       // 16 * 512

    int t = threadIdx.x;
    long s0 = (long)blockIdx.x * 32;

    // load A tile (32 rows of T3)
    const float4* Ag = (const float4*)(g_T3 + s0 * 512);
    float4* A4 = (float4*)As;
#pragma unroll
    for (int i = 0; i < 16; i++) A4[t + 256 * i] = Ag[t + 256 * i];

    int h  = t >> 7;          // sample half: rows h*16 .. h*16+15
    int c0 = (t & 127) * 4;   // 4 consecutive output cols

    float acc[16][4];
#pragma unroll
    for (int j = 0; j < 16; j++)
#pragma unroll
        for (int c = 0; c < 4; c++) acc[j][c] = 0.f;

    for (int k0 = 0; k0 < 512; k0 += 16) {
        __syncthreads();
        const float4* Bg = (const float4*)(g_coreT + (size_t)k0 * 512);
        float4* B4 = (float4*)Bs;
#pragma unroll
        for (int i = 0; i < 8; i++) B4[t + 256 * i] = Bg[t + 256 * i];
        __syncthreads();
#pragma unroll
        for (int kk = 0; kk < 16; kk++) {
            float4 bv = *(const float4*)&Bs[kk * 512 + c0];
#pragma unroll
            for (int j = 0; j < 16; j++) {
                float av = As[(h * 16 + j) * 512 + k0 + kk];
                acc[j][0] += av * bv.x; acc[j][1] += av * bv.y;
                acc[j][2] += av * bv.z; acc[j][3] += av * bv.w;
            }
        }
    }
#pragma unroll
    for (int j = 0; j < 16; j++) {
        float4 v = make_float4(acc[j][0], acc[j][1], acc[j][2], acc[j][3]);
        *(float4*)&g_U[(s0 + h * 16 + j) * 512 + c0] = v;
    }
}

// ---------------- K3: stage C (out-side expansions) ----------------
// Per block: 4 samples, 256 threads. Mirrors K1.
//   u1[a, j*8+k]   = sum_i f0[a*8+i] * U[i*64 + j*8+k]
//   u2[a, b*8+k]   = sum_j f1[b*8+j] * u1[a, j*8+k]
//   y[a*256+b*16+c]= sum_k f2[c*8+k] * u2[a, b*8+k]   (+ bias)
// smem: u1s 4*(16*72) (pad 72), u2s 4*(16*136) (pad 136), factors 3*128
__global__ __launch_bounds__(256) void k_stageC(const float* __restrict__ f0,
                                                const float* __restrict__ f1,
                                                const float* __restrict__ f2,
                                                const float* __restrict__ bias,
                                                float* __restrict__ y) {
    extern __shared__ float sm[];
    float* u1s = sm;                    // 4 * 1152 (16*72)
    float* u2s = sm + 4 * 1152;         // 4 * 2176 (16*136)
    float* f0s = u2s + 4 * 2176;
    float* f1s = f0s + 128;
    float* f2s = f1s + 128;

    int t = threadIdx.x;
    if (t < 128) { f0s[t] = f0[t]; f1s[t] = f1[t]; f2s[t] = f2[t]; }
    __syncthreads();

    long s0 = (long)blockIdx.x * 4;

    // ---- phase 1: u1 (jk column per thread, a-quarter = t>>6, 4 samples) ----
    {
        int g = t >> 6, jk = t & 63;
        float acc[4][4];
#pragma unroll
        for (int s = 0; s < 4; s++)
#pragma unroll
            for (int a4 = 0; a4 < 4; a4++) acc[s][a4] = 0.f;
#pragma unroll
        for (int i = 0; i < 8; i++) {
            float uv0 = g_U[(s0 + 0) * 512 + i * 64 + jk];
            float uv1 = g_U[(s0 + 1) * 512 + i * 64 + jk];
            float uv2 = g_U[(s0 + 2) * 512 + i * 64 + jk];
            float uv3 = g_U[(s0 + 3) * 512 + i * 64 + jk];
#pragma unroll
            for (int a4 = 0; a4 < 4; a4++) {
                float fv = f0s[(g * 4 + a4) * 8 + i];
                acc[0][a4] += uv0 * fv; acc[1][a4] += uv1 * fv;
                acc[2][a4] += uv2 * fv; acc[3][a4] += uv3 * fv;
            }
        }
#pragma unroll
        for (int s = 0; s < 4; s++)
#pragma unroll
            for (int a4 = 0; a4 < 4; a4++)
                u1s[s * 1152 + (g * 4 + a4) * 72 + jk] = acc[s][a4];
    }
    __syncthreads();

    // ---- phase 2: u2 ((a,k) pair per thread, 2 samples) ----
    {
        int h = t >> 7, pair = t & 127;
        int a = pair >> 3, k = pair & 7;
        float acc[2][16];
#pragma unroll
        for (int z = 0; z < 2; z++)
#pragma unroll
            for (int b = 0; b < 16; b++) acc[z][b] = 0.f;
#pragma unroll
        for (int j = 0; j < 8; j++) {
            float tv0 = u1s[(2 * h + 0) * 1152 + a * 72 + j * 8 + k];
            float tv1 = u1s[(2 * h + 1) * 1152 + a * 72 + j * 8 + k];
#pragma unroll
            for (int b = 0; b < 16; b++) {
                float fv = f1s[b * 8 + j];
                acc[0][b] += tv0 * fv; acc[1][b] += tv1 * fv;
            }
        }
#pragma unroll
        for (int z = 0; z < 2; z++)
#pragma unroll
            for (int b = 0; b < 16; b++)
                u2s[(2 * h + z) * 2176 + a * 136 + b * 8 + k] = acc[z][b];
    }
    __syncthreads();

    // ---- phase 3: y (coalesced float4 stores; c-quarter = t&3) ----
    {
        int q = t & 3, ab0 = t >> 2;
#pragma unroll
        for (int r = 0; r < 4; r++) {
            int ab = ab0 + 64 * r;
            int a = ab >> 4, b = ab & 15;
            float acc[4][4];
#pragma unroll
            for (int s = 0; s < 4; s++)
#pragma unroll
                for (int c4 = 0; c4 < 4; c4++) acc[s][c4] = 0.f;
#pragma unroll
            for (int k = 0; k < 8; k++) {
                float tv0 = u2s[0 * 2176 + a * 136 + b * 8 + k];
                float tv1 = u2s[1 * 2176 + a * 136 + b * 8 + k];
                float tv2 = u2s[2 * 2176 + a * 136 + b * 8 + k];
                float tv3 = u2s[3 * 2176 + a * 136 + b * 8 + k];
#pragma unroll
                for (int c4 = 0; c4 < 4; c4++) {
                    float fv = f2s[(q * 4 + c4) * 8 + k];
                    acc[0][c4] += tv0 * fv; acc[1][c4] += tv1 * fv;
                    acc[2][c4] += tv2 * fv; acc[3][c4] += tv3 * fv;
                }
            }
            float4 bv = *(const float4*)&bias[ab * 16 + q * 4];
#pragma unroll
            for (int s = 0; s < 4; s++) {
                float4 o = make_float4(acc[s][0] + bv.x, acc[s][1] + bv.y,
                                       acc[s][2] + bv.z, acc[s][3] + bv.w);
                *(float4*)&y[(s0 + s) * 4096 + ab * 16 + q * 4] = o;
            }
        }
    }
}

// ---------------- launch ----------------
extern "C" void kernel_launch(void* const* d_in, const int* in_sizes, int n_in,
                              void* d_out, int out_size) {
    const float* x    = (const float*)d_in[0];
    const float* core = (const float*)d_in[1];
    const float* f0   = (const float*)d_in[2];
    const float* f1   = (const float*)d_in[3];
    const float* f2   = (const float*)d_in[4];
    const float* f3   = (const float*)d_in[5];
    const float* f4   = (const float*)d_in[6];
    const float* f5   = (const float*)d_in[7];
    const float* bias = (const float*)d_in[8];
    float* y = (float*)d_out;

    int N = in_sizes[0] / 4096;

    const int SMEM_A = (4 * 2048 + 4 * 1088 + 384) * 4;   // 51712
    const int SMEM_G = (32 * 512 + 16 * 512) * 4;          // 98304
    const int SMEM_C = (4 * 1152 + 4 * 2176 + 384) * 4;    // 54784

    cudaFuncSetAttribute(k_stageA, cudaFuncAttributeMaxDynamicSharedMemorySize, SMEM_A);
    cudaFuncSetAttribute(k_gemm,   cudaFuncAttributeMaxDynamicSharedMemorySize, SMEM_G);
    cudaFuncSetAttribute(k_stageC, cudaFuncAttributeMaxDynamicSharedMemorySize, SMEM_C);

    k_transpose<<<dim3(16, 16), dim3(32, 8)>>>(core);
    k_stageA<<<N / 4, 256, SMEM_A>>>(x, f3, f4, f5);
    k_gemm<<<N / 32, 256, SMEM_G>>>();
    k_stageC<<<N / 4, 256, SMEM_C>>>(f0, f1, f2, bias, y);
}

// round 3
// speedup vs baseline: 1.4577x; 1.4577x over previous
#include <cuda_runtime.h>
#include <cstdint>

// ---------------- static device scratch (no allocations allowed) ----------------
__device__ float g_T3[4096 * 512];     // 8 MB : in-contracted activations
__device__ float g_U [4096 * 512];     // 8 MB : core-contracted activations

__device__ __forceinline__ uint32_t f2tf32(float f) {
    uint32_t u;
    asm("cvt.rna.tf32.f32 %0, %1;" : "=r"(u) : "f"(f));
    return u;
}

// ---------------- K1: stage A (in-side contractions) ----------------
// Per block: 4 samples, 256 threads.
__global__ __launch_bounds__(256) void k_stageA(const float* __restrict__ x,
                                                const float* __restrict__ f3,
                                                const float* __restrict__ f4,
                                                const float* __restrict__ f5) {
    extern __shared__ float sm[];
    float* t1s = sm;                    // 4 * 2048
    float* t2s = sm + 4 * 2048;         // 4 * 1088
    float* f3s = t2s + 4 * 1088;
    float* f4s = f3s + 128;
    float* f5s = f4s + 128;

    int t = threadIdx.x;
    if (t < 128) { f3s[t] = f3[t]; f4s[t] = f4[t]; f5s[t] = f5[t]; }
    __syncthreads();

    long s0 = (long)blockIdx.x * 4;

    {
        int ef = t;
        float acc[4][8];
#pragma unroll
        for (int s = 0; s < 4; s++)
#pragma unroll
            for (int l = 0; l < 8; l++) acc[s][l] = 0.f;
#pragma unroll
        for (int d = 0; d < 16; d++) {
            float xv0 = x[(s0 + 0) * 4096 + d * 256 + ef];
            float xv1 = x[(s0 + 1) * 4096 + d * 256 + ef];
            float xv2 = x[(s0 + 2) * 4096 + d * 256 + ef];
            float xv3 = x[(s0 + 3) * 4096 + d * 256 + ef];
#pragma unroll
            for (int l = 0; l < 8; l++) {
                float fv = f3s[d * 8 + l];
                acc[0][l] += xv0 * fv; acc[1][l] += xv1 * fv;
                acc[2][l] += xv2 * fv; acc[3][l] += xv3 * fv;
            }
        }
#pragma unroll
        for (int s = 0; s < 4; s++)
#pragma unroll
            for (int l = 0; l < 8; l++)
                t1s[s * 2048 + l * 256 + ef] = acc[s][l];
    }
    __syncthreads();

    {
        int h = t >> 7, pair = t & 127;
        int l = pair >> 4, f = pair & 15;
        float acc[2][8];
#pragma unroll
        for (int z = 0; z < 2; z++)
#pragma unroll
            for (int m = 0; m < 8; m++) acc[z][m] = 0.f;
#pragma unroll
        for (int e = 0; e < 16; e++) {
            float tv0 = t1s[(2 * h + 0) * 2048 + l * 256 + e * 16 + f];
            float tv1 = t1s[(2 * h + 1) * 2048 + l * 256 + e * 16 + f];
#pragma unroll
            for (int m = 0; m < 8; m++) {
                float fv = f4s[e * 8 + m];
                acc[0][m] += tv0 * fv; acc[1][m] += tv1 * fv;
            }
        }
#pragma unroll
        for (int z = 0; z < 2; z++)
#pragma unroll
            for (int m = 0; m < 8; m++)
                t2s[(2 * h + z) * 1088 + l * 136 + m * 16 + f] = acc[z][m];
    }
    __syncthreads();

    {
        int q = t >> 6, pair = t & 63;
        int l = pair >> 3, m = pair & 7;
        float acc[8];
#pragma unroll
        for (int n = 0; n < 8; n++) acc[n] = 0.f;
#pragma unroll
        for (int f = 0; f < 16; f++) {
            float tv = t2s[q * 1088 + l * 136 + m * 16 + f];
#pragma unroll
            for (int n = 0; n < 8; n++) acc[n] += tv * f5s[f * 8 + n];
        }
        float* dst = g_T3 + (s0 + q) * 512 + l * 64 + m * 8;
        *(float4*)(dst + 0) = make_float4(acc[0], acc[1], acc[2], acc[3]);
        *(float4*)(dst + 4) = make_float4(acc[4], acc[5], acc[6], acc[7]);
    }
}

// ---------------- K2: stage B via mma.sync tf32 ----------------
// U[N,512] = T3[N,512] * core^T.  A = T3 (row-major), B = core [n][k] (K-major native).
// CTA: 128x128 tile, 256 threads (8 warps = 4m x 2n), K chunks of 32, double-buffered.
// smem rows padded to stride 36 words -> fragment LDS conflict-free.
static constexpr int GS = 36;                    // smem row stride (words)
static constexpr int GEMM_SMEM = 4 * 128 * GS * 4;   // 73728 B

__global__ __launch_bounds__(256) void k_gemm_mma(const float* __restrict__ core) {
    extern __shared__ float sm[];
    float* Abuf[2] = { sm,               sm + 128 * GS };
    float* Bbuf[2] = { sm + 2 * 128 * GS, sm + 3 * 128 * GS };

    int t = threadIdx.x;
    int lane = t & 31, wid = t >> 5;
    int warp_m = (wid & 3) * 32;
    int warp_n = (wid >> 2) * 64;
    long s0 = (long)blockIdx.x * 128;
    int n0 = blockIdx.y * 128;

    int lrow = t >> 1;
    int lcol = (t & 1) * 16;

    const float* AG = g_T3 + (s0 + lrow) * 512 + lcol;
    const float* BG = core + (size_t)(n0 + lrow) * 512 + lcol;

    float4 ra[4], rb[4];
    {
        const float4* ap = (const float4*)AG;
        const float4* bp = (const float4*)BG;
#pragma unroll
        for (int j = 0; j < 4; j++) { ra[j] = ap[j]; rb[j] = bp[j]; }
    }

    float acc[2][8][4];
#pragma unroll
    for (int mt = 0; mt < 2; mt++)
#pragma unroll
        for (int nt = 0; nt < 8; nt++)
#pragma unroll
            for (int i = 0; i < 4; i++) acc[mt][nt][i] = 0.f;

    int fr = lane >> 2, fc = lane & 3;   // fragment row-group / k-group

    for (int c = 0; c < 16; c++) {
        int p = c & 1;
        // convert + store current chunk
        {
            float* a_s = Abuf[p] + lrow * GS + lcol;
            float* b_s = Bbuf[p] + lrow * GS + lcol;
#pragma unroll
            for (int j = 0; j < 4; j++) {
                uint4 av = make_uint4(f2tf32(ra[j].x), f2tf32(ra[j].y),
                                      f2tf32(ra[j].z), f2tf32(ra[j].w));
                *(uint4*)(a_s + j * 4) = av;
                uint4 bv = make_uint4(f2tf32(rb[j].x), f2tf32(rb[j].y),
                                      f2tf32(rb[j].z), f2tf32(rb[j].w));
                *(uint4*)(b_s + j * 4) = bv;
            }
        }
        __syncthreads();
        // prefetch next chunk
        if (c < 15) {
            const float4* ap = (const float4*)(AG + (c + 1) * 32);
            const float4* bp = (const float4*)(BG + (c + 1) * 32);
#pragma unroll
            for (int j = 0; j < 4; j++) { ra[j] = ap[j]; rb[j] = bp[j]; }
        }
        // compute on chunk c
        const float* As = Abuf[p];
        const float* Bs = Bbuf[p];
#pragma unroll
        for (int ks = 0; ks < 4; ks++) {
            int k0 = ks * 8;
            uint32_t a[2][4], b[8][2];
#pragma unroll
            for (int mt = 0; mt < 2; mt++) {
                const float* ab = As + (warp_m + mt * 16 + fr) * GS + k0 + fc;
                a[mt][0] = __float_as_uint(ab[0]);
                a[mt][1] = __float_as_uint(ab[8 * GS]);
                a[mt][2] = __float_as_uint(ab[4]);
                a[mt][3] = __float_as_uint(ab[8 * GS + 4]);
            }
#pragma unroll
            for (int nt = 0; nt < 8; nt++) {
                const float* bb = Bs + (warp_n + nt * 8 + fr) * GS + k0 + fc;
                b[nt][0] = __float_as_uint(bb[0]);
                b[nt][1] = __float_as_uint(bb[4]);
            }
#pragma unroll
            for (int mt = 0; mt < 2; mt++)
#pragma unroll
                for (int nt = 0; nt < 8; nt++)
                    asm volatile(
                        "mma.sync.aligned.m16n8k8.row.col.f32.tf32.tf32.f32 "
                        "{%0,%1,%2,%3}, {%4,%5,%6,%7}, {%8,%9}, {%0,%1,%2,%3};"
                        : "+f"(acc[mt][nt][0]), "+f"(acc[mt][nt][1]),
                          "+f"(acc[mt][nt][2]), "+f"(acc[mt][nt][3])
                        : "r"(a[mt][0]), "r"(a[mt][1]), "r"(a[mt][2]), "r"(a[mt][3]),
                          "r"(b[nt][0]), "r"(b[nt][1]));
        }
        __syncthreads();
    }

    // epilogue: c0,c1 -> (row, 2c..2c+1); c2,c3 -> row+8
    int cp = (lane & 3) * 2;
#pragma unroll
    for (int mt = 0; mt < 2; mt++)
#pragma unroll
        for (int h = 0; h < 2; h++) {
            long m = s0 + warp_m + mt * 16 + fr + h * 8;
            float* dst = g_U + m * 512 + n0 + warp_n + cp;
#pragma unroll
            for (int nt = 0; nt < 8; nt++) {
                float2 v = make_float2(acc[mt][nt][h * 2], acc[mt][nt][h * 2 + 1]);
                *(float2*)(dst + nt * 8) = v;
            }
        }
}

// ---------------- K3: stage C (out-side expansions) ----------------
__global__ __launch_bounds__(256) void k_stageC(const float* __restrict__ f0,
                                                const float* __restrict__ f1,
                                                const float* __restrict__ f2,
                                                const float* __restrict__ bias,
                                                float* __restrict__ y) {
    extern __shared__ float sm[];
    float* u1s = sm;                    // 4 * 1152
    float* u2s = sm + 4 * 1152;         // 4 * 2176
    float* f0s = u2s + 4 * 2176;
    float* f1s = f0s + 128;
    float* f2s = f1s + 128;

    int t = threadIdx.x;
    if (t < 128) { f0s[t] = f0[t]; f1s[t] = f1[t]; f2s[t] = f2[t]; }
    __syncthreads();

    long s0 = (long)blockIdx.x * 4;

    {
        int g = t >> 6, jk = t & 63;
        float acc[4][4];
#pragma unroll
        for (int s = 0; s < 4; s++)
#pragma unroll
            for (int a4 = 0; a4 < 4; a4++) acc[s][a4] = 0.f;
#pragma unroll
        for (int i = 0; i < 8; i++) {
            float uv0 = g_U[(s0 + 0) * 512 + i * 64 + jk];
            float uv1 = g_U[(s0 + 1) * 512 + i * 64 + jk];
            float uv2 = g_U[(s0 + 2) * 512 + i * 64 + jk];
            float uv3 = g_U[(s0 + 3) * 512 + i * 64 + jk];
#pragma unroll
            for (int a4 = 0; a4 < 4; a4++) {
                float fv = f0s[(g * 4 + a4) * 8 + i];
                acc[0][a4] += uv0 * fv; acc[1][a4] += uv1 * fv;
                acc[2][a4] += uv2 * fv; acc[3][a4] += uv3 * fv;
            }
        }
#pragma unroll
        for (int s = 0; s < 4; s++)
#pragma unroll
            for (int a4 = 0; a4 < 4; a4++)
                u1s[s * 1152 + (g * 4 + a4) * 72 + jk] = acc[s][a4];
    }
    __syncthreads();

    {
        int h = t >> 7, pair = t & 127;
        int a = pair >> 3, k = pair & 7;
        float acc[2][16];
#pragma unroll
        for (int z = 0; z < 2; z++)
#pragma unroll
            for (int b = 0; b < 16; b++) acc[z][b] = 0.f;
#pragma unroll
        for (int j = 0; j < 8; j++) {
            float tv0 = u1s[(2 * h + 0) * 1152 + a * 72 + j * 8 + k];
            float tv1 = u1s[(2 * h + 1) * 1152 + a * 72 + j * 8 + k];
#pragma unroll
            for (int b = 0; b < 16; b++) {
                float fv = f1s[b * 8 + j];
                acc[0][b] += tv0 * fv; acc[1][b] += tv1 * fv;
            }
        }
#pragma unroll
        for (int z = 0; z < 2; z++)
#pragma unroll
            for (int b = 0; b < 16; b++)
                u2s[(2 * h + z) * 2176 + a * 136 + b * 8 + k] = acc[z][b];
    }
    __syncthreads();

    {
        int q = t & 3, ab0 = t >> 2;
#pragma unroll
        for (int r = 0; r < 4; r++) {
            int ab = ab0 + 64 * r;
            int a = ab >> 4, b = ab & 15;
            float acc[4][4];
#pragma unroll
            for (int s = 0; s < 4; s++)
#pragma unroll
                for (int c4 = 0; c4 < 4; c4++) acc[s][c4] = 0.f;
#pragma unroll
            for (int k = 0; k < 8; k++) {
                float tv0 = u2s[0 * 2176 + a * 136 + b * 8 + k];
                float tv1 = u2s[1 * 2176 + a * 136 + b * 8 + k];
                float tv2 = u2s[2 * 2176 + a * 136 + b * 8 + k];
                float tv3 = u2s[3 * 2176 + a * 136 + b * 8 + k];
#pragma unroll
                for (int c4 = 0; c4 < 4; c4++) {
                    float fv = f2s[(q * 4 + c4) * 8 + k];
                    acc[0][c4] += tv0 * fv; acc[1][c4] += tv1 * fv;
                    acc[2][c4] += tv2 * fv; acc[3][c4] += tv3 * fv;
                }
            }
            float4 bv = *(const float4*)&bias[ab * 16 + q * 4];
#pragma unroll
            for (int s = 0; s < 4; s++) {
                float4 o = make_float4(acc[s][0] + bv.x, acc[s][1] + bv.y,
                                       acc[s][2] + bv.z, acc[s][3] + bv.w);
                *(float4*)&y[(s0 + s) * 4096 + ab * 16 + q * 4] = o;
            }
        }
    }
}

// ---------------- launch ----------------
extern "C" void kernel_launch(void* const* d_in, const int* in_sizes, int n_in,
                              void* d_out, int out_size) {
    const float* x    = (const float*)d_in[0];
    const float* core = (const float*)d_in[1];
    const float* f0   = (const float*)d_in[2];
    const float* f1   = (const float*)d_in[3];
    const float* f2   = (const float*)d_in[4];
    const float* f3   = (const float*)d_in[5];
    const float* f4   = (const float*)d_in[6];
    const float* f5   = (const float*)d_in[7];
    const float* bias = (const float*)d_in[8];
    float* y = (float*)d_out;

    int N = in_sizes[0] / 4096;

    const int SMEM_A = (4 * 2048 + 4 * 1088 + 384) * 4;   // 51712
    const int SMEM_C = (4 * 1152 + 4 * 2176 + 384) * 4;   // 54784

    cudaFuncSetAttribute(k_stageA, cudaFuncAttributeMaxDynamicSharedMemorySize, SMEM_A);
    cudaFuncSetAttribute(k_gemm_mma, cudaFuncAttributeMaxDynamicSharedMemorySize, GEMM_SMEM);
    cudaFuncSetAttribute(k_stageC, cudaFuncAttributeMaxDynamicSharedMemorySize, SMEM_C);

    k_stageA<<<N / 4, 256, SMEM_A>>>(x, f3, f4, f5);
    k_gemm_mma<<<dim3(N / 128, 4), 256, GEMM_SMEM>>>(core);
    k_stageC<<<N / 4, 256, SMEM_C>>>(f0, f1, f2, bias, y);
}

// round 4
// speedup vs baseline: 1.5861x; 1.0881x over previous
#include <cuda_runtime.h>
#include <cstdint>

// ---------------- static device scratch (no allocations allowed) ----------------
__device__ float g_T3[4096 * 512];      // 8 MB : in-contracted activations (tf32 bits)
__device__ float g_U [4096 * 512];      // 8 MB : core-contracted activations (fp32)
__device__ float g_coreTF[512 * 512];   // 1 MB : core pre-converted to tf32 bits

__device__ __forceinline__ uint32_t f2tf32(float f) {
    uint32_t u;
    asm("cvt.rna.tf32.f32 %0, %1;" : "=r"(u) : "f"(f));
    return u;
}
__device__ __forceinline__ uint32_t smem_u32(const void* p) {
    uint32_t a;
    asm("{ .reg .u64 t; cvta.to.shared.u64 t, %1; cvt.u32.u64 %0, t; }" : "=r"(a) : "l"(p));
    return a;
}
#define CP_ASYNC16(dst, src) \
    asm volatile("cp.async.cg.shared.global [%0], [%1], 16;" :: "r"(dst), "l"(src) : "memory")
#define CP_COMMIT() asm volatile("cp.async.commit_group;" ::: "memory")
#define CP_WAIT(n)  asm volatile("cp.async.wait_group %0;" :: "n"(n) : "memory")

// ---------------- K0: pre-convert core to tf32 bits ----------------
__global__ __launch_bounds__(256) void k_cvtcore(const float* __restrict__ core) {
    int i = (blockIdx.x * 256 + threadIdx.x) * 4;
    float4 v = *(const float4*)(core + i);
    uint4 o = make_uint4(f2tf32(v.x), f2tf32(v.y), f2tf32(v.z), f2tf32(v.w));
    *(uint4*)(g_coreTF + i) = o;
}

// ---------------- K1: stage A, warp-per-sample ----------------
// 8 samples/block (one per warp), 256 threads, no block barriers in main body.
//   t1[l, ef]      = sum_d x[d*256+ef] * f3[d,l]        (stride 272 per l)
//   t2[l, m, f]    = sum_e t1[l, e*16+f] * f4[e,m]      (strides 144 / 17)
//   t3[l*64+m*8+n] = sum_f t2[l, m, f] * f5[f,n]  -> g_T3 as tf32 bits
static constexpr int T1L = 272;   // per-l stride of t1 (16-float pad)
static constexpr int T2L = 144;   // per-l stride of t2
static constexpr int WSM = 8 * T1L + 8 * T2L;               // 3328 floats / warp
static constexpr int SMEM_A = (8 * WSM + 384) * 4;          // 108032 B

__global__ __launch_bounds__(256, 2) void k_stageA(const float* __restrict__ x,
                                                   const float* __restrict__ f3,
                                                   const float* __restrict__ f4,
                                                   const float* __restrict__ f5) {
    extern __shared__ float sm[];
    float* f3s = sm + 8 * WSM;
    float* f4s = f3s + 128;
    float* f5s = f4s + 128;

    int t = threadIdx.x, wid = t >> 5, lane = t & 31;
    if (t < 128) { f3s[t] = f3[t]; f4s[t] = f4[t]; f5s[t] = f5[t]; }
    __syncthreads();

    float* t1w = sm + wid * WSM;            // 8 * 272
    float* t2w = t1w + 8 * T1L;             // 8 * 144

    long s = (long)blockIdx.x * 8 + wid;
    const float* xs = x + s * 4096;

    // ---- phase 1: t1 ----
    {
        float acc[8][8];   // [j][l]
#pragma unroll
        for (int j = 0; j < 8; j++)
#pragma unroll
            for (int l = 0; l < 8; l++) acc[j][l] = 0.f;
#pragma unroll 4
        for (int d = 0; d < 16; d++) {
            float xv[8];
#pragma unroll
            for (int j = 0; j < 8; j++) xv[j] = xs[d * 256 + lane + 32 * j];
#pragma unroll
            for (int l = 0; l < 8; l++) {
                float fv = f3s[d * 8 + l];
#pragma unroll
                for (int j = 0; j < 8; j++) acc[j][l] += xv[j] * fv;
            }
        }
#pragma unroll
        for (int l = 0; l < 8; l++)
#pragma unroll
            for (int j = 0; j < 8; j++)
                t1w[l * T1L + lane + 32 * j] = acc[j][l];
    }
    __syncwarp();

    // ---- phase 2: t2 (4 (l,f) pairs per lane) ----
    {
        float acc[4][8];   // [q][m]
#pragma unroll
        for (int q = 0; q < 4; q++)
#pragma unroll
            for (int m = 0; m < 8; m++) acc[q][m] = 0.f;
#pragma unroll
        for (int e = 0; e < 16; e++) {
            float tv[4];
#pragma unroll
            for (int q = 0; q < 4; q++) {
                int p = lane + 32 * q, l = p >> 4, f = p & 15;
                tv[q] = t1w[l * T1L + e * 16 + f];
            }
#pragma unroll
            for (int m = 0; m < 8; m++) {
                float fv = f4s[e * 8 + m];
#pragma unroll
                for (int q = 0; q < 4; q++) acc[q][m] += tv[q] * fv;
            }
        }
#pragma unroll
        for (int q = 0; q < 4; q++) {
            int p = lane + 32 * q, l = p >> 4, f = p & 15;
#pragma unroll
            for (int m = 0; m < 8; m++)
                t2w[l * T2L + m * 17 + f] = acc[q][m];
        }
    }
    __syncwarp();

    // ---- phase 3: t3 -> g_T3 (tf32 bits), 2 (l,m) pairs per lane ----
    {
#pragma unroll
        for (int h = 0; h < 2; h++) {
            int lm = lane + 32 * h, l = lm >> 3, m = lm & 7;
            float acc[8];
#pragma unroll
            for (int n = 0; n < 8; n++) acc[n] = 0.f;
#pragma unroll
            for (int f = 0; f < 16; f++) {
                float tv = t2w[l * T2L + m * 17 + f];
#pragma unroll
                for (int n = 0; n < 8; n++) acc[n] += tv * f5s[f * 8 + n];
            }
            uint4* dst = (uint4*)(g_T3 + s * 512 + lm * 8);
            dst[0] = make_uint4(f2tf32(acc[0]), f2tf32(acc[1]), f2tf32(acc[2]), f2tf32(acc[3]));
            dst[1] = make_uint4(f2tf32(acc[4]), f2tf32(acc[5]), f2tf32(acc[6]), f2tf32(acc[7]));
        }
    }
}

// ---------------- K2: stage B via mma.sync tf32 + cp.async pipeline ----------------
// U[N,512] = T3[N,512] * core^T.  Operands pre-converted to tf32 bits.
// CTA: 128x128 tile, 256 threads (8 warps = 4m x 2n), K chunks of 32, double-buffered.
static constexpr int GS = 36;                        // smem row stride (words)
static constexpr int GEMM_SMEM = 4 * 128 * GS * 4;   // 73728 B

__global__ __launch_bounds__(256) void k_gemm_mma() {
    extern __shared__ float sm[];
    float* Abuf[2] = { sm,                sm + 128 * GS };
    float* Bbuf[2] = { sm + 2 * 128 * GS, sm + 3 * 128 * GS };
    uint32_t sm_u = smem_u32(sm);
    uint32_t Au[2] = { sm_u,                   sm_u + 128 * GS * 4 };
    uint32_t Bu[2] = { sm_u + 2 * 128 * GS * 4, sm_u + 3 * 128 * GS * 4 };

    int t = threadIdx.x;
    int lane = t & 31, wid = t >> 5;
    int warp_m = (wid & 3) * 32;
    int warp_n = (wid >> 2) * 64;
    long s0 = (long)blockIdx.x * 128;
    int n0 = blockIdx.y * 128;

    int lrow = t >> 1;
    int lhalf = t & 1;            // 16-float half of the 32-col chunk
    const float* AG = g_T3 + (s0 + lrow) * 512 + lhalf * 16;
    const float* BG = g_coreTF + (size_t)(n0 + lrow) * 512 + lhalf * 16;
    uint32_t a_dst = (uint32_t)((lrow * GS + lhalf * 16) * 4);

    float acc[2][8][4];
#pragma unroll
    for (int mt = 0; mt < 2; mt++)
#pragma unroll
        for (int nt = 0; nt < 8; nt++)
#pragma unroll
            for (int i = 0; i < 4; i++) acc[mt][nt][i] = 0.f;

    int fr = lane >> 2, fc = lane & 3;

    // issue chunk 0
    {
#pragma unroll
        for (int i = 0; i < 4; i++) {
            CP_ASYNC16(Au[0] + a_dst + i * 16, AG + i * 4);
            CP_ASYNC16(Bu[0] + a_dst + i * 16, BG + i * 4);
        }
        CP_COMMIT();
    }

    for (int c = 0; c < 16; c++) {
        int p = c & 1;
        if (c + 1 < 16) {
            int pn = (c + 1) & 1;
            const float* ag = AG + (c + 1) * 32;
            const float* bg = BG + (c + 1) * 32;
#pragma unroll
            for (int i = 0; i < 4; i++) {
                CP_ASYNC16(Au[pn] + a_dst + i * 16, ag + i * 4);
                CP_ASYNC16(Bu[pn] + a_dst + i * 16, bg + i * 4);
            }
            CP_COMMIT();
            CP_WAIT(1);
        } else {
            CP_WAIT(0);
        }
        __syncthreads();

        const float* As = Abuf[p];
        const float* Bs = Bbuf[p];
#pragma unroll
        for (int ks = 0; ks < 4; ks++) {
            int k0 = ks * 8;
            uint32_t a[2][4], b[8][2];
#pragma unroll
            for (int mt = 0; mt < 2; mt++) {
                const float* ab = As + (warp_m + mt * 16 + fr) * GS + k0 + fc;
                a[mt][0] = __float_as_uint(ab[0]);
                a[mt][1] = __float_as_uint(ab[8 * GS]);
                a[mt][2] = __float_as_uint(ab[4]);
                a[mt][3] = __float_as_uint(ab[8 * GS + 4]);
            }
#pragma unroll
            for (int nt = 0; nt < 8; nt++) {
                const float* bb = Bs + (warp_n + nt * 8 + fr) * GS + k0 + fc;
                b[nt][0] = __float_as_uint(bb[0]);
                b[nt][1] = __float_as_uint(bb[4]);
            }
#pragma unroll
            for (int mt = 0; mt < 2; mt++)
#pragma unroll
                for (int nt = 0; nt < 8; nt++)
                    asm volatile(
                        "mma.sync.aligned.m16n8k8.row.col.f32.tf32.tf32.f32 "
                        "{%0,%1,%2,%3}, {%4,%5,%6,%7}, {%8,%9}, {%0,%1,%2,%3};"
                        : "+f"(acc[mt][nt][0]), "+f"(acc[mt][nt][1]),
                          "+f"(acc[mt][nt][2]), "+f"(acc[mt][nt][3])
                        : "r"(a[mt][0]), "r"(a[mt][1]), "r"(a[mt][2]), "r"(a[mt][3]),
                          "r"(b[nt][0]), "r"(b[nt][1]));
        }
        __syncthreads();
    }

    // epilogue
    int cp = (lane & 3) * 2;
#pragma unroll
    for (int mt = 0; mt < 2; mt++)
#pragma unroll
        for (int h = 0; h < 2; h++) {
            long m = s0 + warp_m + mt * 16 + fr + h * 8;
            float* dst = g_U + m * 512 + n0 + warp_n + cp;
#pragma unroll
            for (int nt = 0; nt < 8; nt++) {
                float2 v = make_float2(acc[mt][nt][h * 2], acc[mt][nt][h * 2 + 1]);
                *(float2*)(dst + nt * 8) = v;
            }
        }
}

// ---------------- K3: stage C (out-side expansions) ----------------
__global__ __launch_bounds__(256) void k_stageC(const float* __restrict__ f0,
                                                const float* __restrict__ f1,
                                                const float* __restrict__ f2,
                                                const float* __restrict__ bias,
                                                float* __restrict__ y) {
    extern __shared__ float sm[];
    float* u1s = sm;                    // 4 * 1152
    float* u2s = sm + 4 * 1152;         // 4 * 2176
    float* f0s = u2s + 4 * 2176;
    float* f1s = f0s + 128;
    float* f2s = f1s + 128;

    int t = threadIdx.x;
    if (t < 128) { f0s[t] = f0[t]; f1s[t] = f1[t]; f2s[t] = f2[t]; }
    __syncthreads();

    long s0 = (long)blockIdx.x * 4;

    {
        int g = t >> 6, jk = t & 63;
        float acc[4][4];
#pragma unroll
        for (int s = 0; s < 4; s++)
#pragma unroll
            for (int a4 = 0; a4 < 4; a4++) acc[s][a4] = 0.f;
#pragma unroll
        for (int i = 0; i < 8; i++) {
            float uv0 = g_U[(s0 + 0) * 512 + i * 64 + jk];
            float uv1 = g_U[(s0 + 1) * 512 + i * 64 + jk];
            float uv2 = g_U[(s0 + 2) * 512 + i * 64 + jk];
            float uv3 = g_U[(s0 + 3) * 512 + i * 64 + jk];
#pragma unroll
            for (int a4 = 0; a4 < 4; a4++) {
                float fv = f0s[(g * 4 + a4) * 8 + i];
                acc[0][a4] += uv0 * fv; acc[1][a4] += uv1 * fv;
                acc[2][a4] += uv2 * fv; acc[3][a4] += uv3 * fv;
            }
        }
#pragma unroll
        for (int s = 0; s < 4; s++)
#pragma unroll
            for (int a4 = 0; a4 < 4; a4++)
                u1s[s * 1152 + (g * 4 + a4) * 72 + jk] = acc[s][a4];
    }
    __syncthreads();

    {
        int h = t >> 7, pair = t & 127;
        int a = pair >> 3, k = pair & 7;
        float acc[2][16];
#pragma unroll
        for (int z = 0; z < 2; z++)
#pragma unroll
            for (int b = 0; b < 16; b++) acc[z][b] = 0.f;
#pragma unroll
        for (int j = 0; j < 8; j++) {
            float tv0 = u1s[(2 * h + 0) * 1152 + a * 72 + j * 8 + k];
            float tv1 = u1s[(2 * h + 1) * 1152 + a * 72 + j * 8 + k];
#pragma unroll
            for (int b = 0; b < 16; b++) {
                float fv = f1s[b * 8 + j];
                acc[0][b] += tv0 * fv; acc[1][b] += tv1 * fv;
            }
        }
#pragma unroll
        for (int z = 0; z < 2; z++)
#pragma unroll
            for (int b = 0; b < 16; b++)
                u2s[(2 * h + z) * 2176 + a * 136 + b * 8 + k] = acc[z][b];
    }
    __syncthreads();

    {
        int q = t & 3, ab0 = t >> 2;
#pragma unroll
        for (int r = 0; r < 4; r++) {
            int ab = ab0 + 64 * r;
            int a = ab >> 4, b = ab & 15;
            float acc[4][4];
#pragma unroll
            for (int s = 0; s < 4; s++)
#pragma unroll
                for (int c4 = 0; c4 < 4; c4++) acc[s][c4] = 0.f;
#pragma unroll
            for (int k = 0; k < 8; k++) {
                float tv0 = u2s[0 * 2176 + a * 136 + b * 8 + k];
                float tv1 = u2s[1 * 2176 + a * 136 + b * 8 + k];
                float tv2 = u2s[2 * 2176 + a * 136 + b * 8 + k];
                float tv3 = u2s[3 * 2176 + a * 136 + b * 8 + k];
#pragma unroll
                for (int c4 = 0; c4 < 4; c4++) {
                    float fv = f2s[(q * 4 + c4) * 8 + k];
                    acc[0][c4] += tv0 * fv; acc[1][c4] += tv1 * fv;
                    acc[2][c4] += tv2 * fv; acc[3][c4] += tv3 * fv;
                }
            }
            float4 bv = *(const float4*)&bias[ab * 16 + q * 4];
#pragma unroll
            for (int s = 0; s < 4; s++) {
                float4 o = make_float4(acc[s][0] + bv.x, acc[s][1] + bv.y,
                                       acc[s][2] + bv.z, acc[s][3] + bv.w);
                *(float4*)&y[(s0 + s) * 4096 + ab * 16 + q * 4] = o;
            }
        }
    }
}

// ---------------- launch ----------------
extern "C" void kernel_launch(void* const* d_in, const int* in_sizes, int n_in,
                              void* d_out, int out_size) {
    const float* x    = (const float*)d_in[0];
    const float* core = (const float*)d_in[1];
    const float* f0   = (const float*)d_in[2];
    const float* f1   = (const float*)d_in[3];
    const float* f2   = (const float*)d_in[4];
    const float* f3   = (const float*)d_in[5];
    const float* f4   = (const float*)d_in[6];
    const float* f5   = (const float*)d_in[7];
    const float* bias = (const float*)d_in[8];
    float* y = (float*)d_out;

    int N = in_sizes[0] / 4096;

    const int SMEM_C = (4 * 1152 + 4 * 2176 + 384) * 4;   // 54784

    cudaFuncSetAttribute(k_stageA, cudaFuncAttributeMaxDynamicSharedMemorySize, SMEM_A);
    cudaFuncSetAttribute(k_gemm_mma, cudaFuncAttributeMaxDynamicSharedMemorySize, GEMM_SMEM);
    cudaFuncSetAttribute(k_stageC, cudaFuncAttributeMaxDynamicSharedMemorySize, SMEM_C);

    k_cvtcore<<<256, 256>>>(core);
    k_stageA<<<N / 8, 256, SMEM_A>>>(x, f3, f4, f5);
    k_gemm_mma<<<dim3(N / 128, 4), 256, GEMM_SMEM>>>();
    k_stageC<<<N / 4, 256, SMEM_C>>>(f0, f1, f2, bias, y);
}